// round 3
// baseline (speedup 1.0000x reference)
#include <cuda_runtime.h>
#include <cuda_bf16.h>

// Problem constants
#define BB   256
#define LL   2048
#define DD   128
#define VV   6000
#define TMAX 48

// Precomputed exp(embW) table (V+1 entries). __device__ global scratch is the
// allowed mechanism (no cudaMalloc permitted).
__device__ float g_wtab[VV + 1];

// Kernel 0: wtab[v] = exp(embW[v]). ~6K threads, negligible cost.
__global__ void wtab_kernel(const float* __restrict__ embW) {
    int i = blockIdx.x * blockDim.x + threadIdx.x;
    if (i < VV + 1) g_wtab[i] = __expf(embW[i]);
}

// Kernel 1: one CTA per batch row b.
//   Phase 0: load (T, id) meta, CTA-local counting sort by bin (48 bins).
//   Phase 1: warp-per-bin register accumulation, direct output write.
__global__ void __launch_bounds__(512, 2)
embedder_kernel(const float* __restrict__ X,
                const float* __restrict__ embX,
                float* __restrict__ out) {
    const int b    = blockIdx.x;
    const int tid  = threadIdx.x;
    const int warp = tid >> 5;
    const int lane = tid & 31;

    __shared__ int s_meta[LL];          // packed (bin<<13)|id
    __shared__ int s_sorted[LL];        // ids, bin-sorted
    __shared__ int s_hist[TMAX];
    __shared__ int s_off[TMAX + 1];
    __shared__ int s_cur[TMAX];

    if (tid < TMAX) s_hist[tid] = 0;
    __syncthreads();

    // ---------- Phase 0a: load meta + histogram ----------
    const float2* Xb = reinterpret_cast<const float2*>(X + (size_t)b * LL * 2);
    #pragma unroll 1
    for (int t = tid; t < LL; t += 512) {
        float2 m = Xb[t];                       // m.x = T, m.y = id (float)
        int bin = (int)floorf(m.x);
        bin = min(max(bin, 0), TMAX - 1);
        int id = (int)m.y;                      // 1..5999, exact in fp32
        s_meta[t] = (bin << 13) | id;
        atomicAdd(&s_hist[bin], 1);
    }
    __syncthreads();

    // ---------- Phase 0b: exclusive prefix over 48 bins (1 thread, trivial) ----------
    if (tid == 0) {
        int acc = 0;
        #pragma unroll
        for (int i = 0; i < TMAX; i++) {
            s_off[i] = acc;
            s_cur[i] = acc;
            acc += s_hist[i];
        }
        s_off[TMAX] = acc;
    }
    __syncthreads();

    // ---------- Phase 0c: scatter ids into bin-sorted order ----------
    #pragma unroll 1
    for (int t = tid; t < LL; t += 512) {
        int m   = s_meta[t];
        int bin = m >> 13;
        int id  = m & 8191;
        int pos = atomicAdd(&s_cur[bin], 1);
        s_sorted[pos] = id;
    }
    __syncthreads();

    // ---------- Phase 1: each warp owns bins {warp, warp+16, warp+32} ----------
    // Lane covers D-slice [4*lane, 4*lane+4) as float4. Pure register accumulation.
    for (int bin = warp; bin < TMAX; bin += 16) {
        const int beg = s_off[bin];
        const int end = s_off[bin + 1];

        float ax = 0.f, ay = 0.f, az = 0.f, aw = 0.f;

        int i = beg;
        // Unroll-by-4 for MLP over the ~250-cycle L2 gather latency.
        for (; i + 4 <= end; i += 4) {
            int id0 = s_sorted[i + 0];
            int id1 = s_sorted[i + 1];
            int id2 = s_sorted[i + 2];
            int id3 = s_sorted[i + 3];

            float w0 = g_wtab[id0];
            float w1 = g_wtab[id1];
            float w2 = g_wtab[id2];
            float w3 = g_wtab[id3];

            float4 e0 = __ldg(reinterpret_cast<const float4*>(embX + (size_t)id0 * DD) + lane);
            float4 e1 = __ldg(reinterpret_cast<const float4*>(embX + (size_t)id1 * DD) + lane);
            float4 e2 = __ldg(reinterpret_cast<const float4*>(embX + (size_t)id2 * DD) + lane);
            float4 e3 = __ldg(reinterpret_cast<const float4*>(embX + (size_t)id3 * DD) + lane);

            ax = fmaf(w0, e0.x, ax); ay = fmaf(w0, e0.y, ay);
            az = fmaf(w0, e0.z, az); aw = fmaf(w0, e0.w, aw);
            ax = fmaf(w1, e1.x, ax); ay = fmaf(w1, e1.y, ay);
            az = fmaf(w1, e1.z, az); aw = fmaf(w1, e1.w, aw);
            ax = fmaf(w2, e2.x, ax); ay = fmaf(w2, e2.y, ay);
            az = fmaf(w2, e2.z, az); aw = fmaf(w2, e2.w, aw);
            ax = fmaf(w3, e3.x, ax); ay = fmaf(w3, e3.y, ay);
            az = fmaf(w3, e3.z, az); aw = fmaf(w3, e3.w, aw);
        }
        for (; i < end; i++) {
            int id = s_sorted[i];
            float w = g_wtab[id];
            float4 e = __ldg(reinterpret_cast<const float4*>(embX + (size_t)id * DD) + lane);
            ax = fmaf(w, e.x, ax); ay = fmaf(w, e.y, ay);
            az = fmaf(w, e.z, az); aw = fmaf(w, e.w, aw);
        }

        const float inv = 1.0f / ((float)(end - beg) + 1e-6f);
        float4 o;
        o.x = ax * inv; o.y = ay * inv; o.z = az * inv; o.w = aw * inv;
        reinterpret_cast<float4*>(out + ((size_t)b * TMAX + bin) * DD)[lane] = o;
    }
}

extern "C" void kernel_launch(void* const* d_in, const int* in_sizes, int n_in,
                              void* d_out, int out_size) {
    const float* X    = (const float*)d_in[0];   // [B, L, 2] fp32
    const float* embX = (const float*)d_in[1];   // [V, D] fp32
    const float* embW = (const float*)d_in[2];   // [V+1, 1] fp32
    float* out = (float*)d_out;                  // [B, TMAX, D] fp32

    wtab_kernel<<<(VV + 1 + 255) / 256, 256>>>(embW);
    embedder_kernel<<<BB, 512>>>(X, embX, out);
}

// round 6
// speedup vs baseline: 1.2889x; 1.2889x over previous
#include <cuda_runtime.h>
#include <cuda_bf16.h>

// Problem constants
#define BB   256
#define LL   2048
#define DD   128
#define VV   6000
#define TMAX 48

#define NTHREADS 512
#define NWARPS   16
#define SORT_CAP (LL + TMAX * 4)   // padded counting-sort capacity

// Pre-scaled embedding table: g_scaled[v][d] = exp(embW[v]) * embX[v][d].
// 3MB __device__ scratch (allowed; no cudaMalloc).
__device__ float g_scaled[(size_t)VV * DD];

// Kernel 0: build the scaled table. float4 lanes, ~1us.
__global__ void scale_kernel(const float* __restrict__ embX,
                             const float* __restrict__ embW) {
    int idx = blockIdx.x * blockDim.x + threadIdx.x;   // float4 index
    if (idx < VV * (DD / 4)) {
        int v = idx >> 5;                               // 32 float4 per row
        float w = __expf(__ldg(embW + v));
        float4 e = reinterpret_cast<const float4*>(embX)[idx];
        reinterpret_cast<float4*>(g_scaled)[idx] =
            make_float4(e.x * w, e.y * w, e.z * w, e.w * w);
    }
}

// Kernel 1: one CTA per batch row.
//   Phase 0: atomic-free counting sort of 2048 tokens into 48 time bins
//            (warp-private histograms via __match_any_sync, hierarchical
//            cursors, bins padded to multiples of 4 with id=0 == zero row).
//   Phase 1: rank-balanced warp-per-bin register accumulation from the
//            pre-scaled table; direct normalized output write.
__global__ void __launch_bounds__(NTHREADS, 2)
embedder_kernel(const float* __restrict__ X, float* __restrict__ out) {
    const int b    = blockIdx.x;
    const int tid  = threadIdx.x;
    const int warp = tid >> 5;
    const int lane = tid & 31;

    __shared__ __align__(16) int s_sorted[SORT_CAP];   // bin-sorted ids (padded with 0)
    __shared__ int s_meta[LL];                          // packed (bin<<13)|id
    __shared__ int s_whist[NWARPS * TMAX];              // per-warp bin counts
    __shared__ int s_wcur[NWARPS * TMAX];               // per-(warp,bin) cursors
    __shared__ int s_hist[TMAX];                        // true bin counts
    __shared__ int s_offP[TMAX + 1];                    // padded bin offsets
    __shared__ int s_assign[TMAX];                      // (warp,slot) -> bin

    for (int i = tid; i < SORT_CAP; i += NTHREADS) s_sorted[i] = 0;
    for (int i = tid; i < NWARPS * TMAX; i += NTHREADS) s_whist[i] = 0;
    __syncthreads();

    // ---------- Phase 0a: load meta + warp-private histogram (no atomics) ----------
    const float2* Xb = reinterpret_cast<const float2*>(X) + (size_t)b * LL;
    #pragma unroll
    for (int it = 0; it < LL / NTHREADS; ++it) {
        int t = it * NTHREADS + tid;
        float2 m = Xb[t];                    // m.x = T (>=0), m.y = id
        int bin = (int)m.x;                  // trunc == floor for T >= 0
        bin = min(max(bin, 0), TMAX - 1);
        int id = (int)m.y;                   // 1..5999, exact in fp32
        s_meta[t] = (bin << 13) | id;
        unsigned g = __match_any_sync(0xffffffffu, bin);
        if ((int)(__ffs(g) - 1) == lane)     // leader: plain RMW, race-free
            s_whist[warp * TMAX + bin] += __popc(g);
    }
    __syncthreads();

    // ---------- Phase 0b: totals ----------
    if (tid < TMAX) {
        int c = 0;
        #pragma unroll
        for (int w = 0; w < NWARPS; w++) c += s_whist[w * TMAX + tid];
        s_hist[tid] = c;
    }
    __syncthreads();

    // Rank bins by count (parallel, 48 threads) + snake-partition into warps.
    if (tid < TMAX) {
        int c = s_hist[tid];
        int r = 0;
        #pragma unroll 8
        for (int j = 0; j < TMAX; j++) {
            int cj = s_hist[j];
            r += (cj > c) || (cj == c && j < tid);
        }
        int w, slot;
        if (r < NWARPS)            { w = r;                  slot = 0; }
        else if (r < 2 * NWARPS)   { w = 2 * NWARPS - 1 - r; slot = 1; }
        else                       { w = r - 2 * NWARPS;     slot = 2; }
        s_assign[w * 3 + slot] = tid;
    }
    // Padded exclusive prefix (48 serial iters, ~300 cyc).
    if (tid == 0) {
        int acc = 0;
        #pragma unroll
        for (int i = 0; i < TMAX; i++) {
            s_offP[i] = acc;
            acc += (s_hist[i] + 3) & ~3;     // pad each bin to x4 (pad ids = 0 = zero row)
        }
        s_offP[TMAX] = acc;
    }
    __syncthreads();

    // Per-(warp,bin) scatter cursors: offP[bin] + sum of earlier warps' counts.
    for (int i = tid; i < NWARPS * TMAX; i += NTHREADS) {
        int w = i / TMAX, bin = i - w * TMAX;
        int c = s_offP[bin];
        for (int w2 = 0; w2 < w; w2++) c += s_whist[w2 * TMAX + bin];
        s_wcur[i] = c;
    }
    __syncthreads();

    // ---------- Phase 0c: atomic-free scatter (same token order as 0a) ----------
    #pragma unroll
    for (int it = 0; it < LL / NTHREADS; ++it) {
        int t = it * NTHREADS + tid;
        int m = s_meta[t];
        int bin = m >> 13;
        unsigned g = __match_any_sync(0xffffffffu, bin);
        int leader = __ffs(g) - 1;
        int rank = __popc(g & ((1u << lane) - 1u));
        int base = 0;
        if (lane == leader) {
            base = s_wcur[warp * TMAX + bin];
            s_wcur[warp * TMAX + bin] = base + __popc(g);
        }
        base = __shfl_sync(0xffffffffu, base, leader);
        s_sorted[base + rank] = m & 8191;
    }
    __syncthreads();

    // ---------- Phase 1: balanced warp-per-bin register accumulation ----------
    const float4* __restrict__ tab = reinterpret_cast<const float4*>(g_scaled);
    #pragma unroll 1
    for (int slot = 0; slot < 3; ++slot) {
        const int bin = s_assign[warp * 3 + slot];
        const int beg = s_offP[bin];
        const int end = s_offP[bin + 1];     // padded; (end-beg) % 4 == 0
        const int cnt = s_hist[bin];         // hoisted off the epilogue chain

        float ax = 0.f, ay = 0.f, az = 0.f, aw = 0.f;

        #pragma unroll 1
        for (int i = beg; i < end; i += 4) {
            int4 ids = *reinterpret_cast<const int4*>(s_sorted + i);  // 16B-aligned broadcast
            float4 e0 = __ldg(tab + ids.x * (DD / 4) + lane);
            float4 e1 = __ldg(tab + ids.y * (DD / 4) + lane);
            float4 e2 = __ldg(tab + ids.z * (DD / 4) + lane);
            float4 e3 = __ldg(tab + ids.w * (DD / 4) + lane);
            ax += (e0.x + e1.x) + (e2.x + e3.x);
            ay += (e0.y + e1.y) + (e2.y + e3.y);
            az += (e0.z + e1.z) + (e2.z + e3.z);
            aw += (e0.w + e1.w) + (e2.w + e3.w);
        }

        const float inv = 1.0f / ((float)cnt + 1e-6f);
        float4 o = make_float4(ax * inv, ay * inv, az * inv, aw * inv);
        reinterpret_cast<float4*>(out + ((size_t)b * TMAX + bin) * DD)[lane] = o;
    }
}

extern "C" void kernel_launch(void* const* d_in, const int* in_sizes, int n_in,
                              void* d_out, int out_size) {
    const float* X    = (const float*)d_in[0];   // [B, L, 2] fp32
    const float* embX = (const float*)d_in[1];   // [V, D] fp32
    const float* embW = (const float*)d_in[2];   // [V+1, 1] fp32
    float* out = (float*)d_out;                  // [B, TMAX, D] fp32

    scale_kernel<<<(VV * (DD / 4) + 255) / 256, 256>>>(embX, embW);
    embedder_kernel<<<BB, NTHREADS>>>(X, out);
}